// round 7
// baseline (speedup 1.0000x reference)
#include <cuda_runtime.h>
#include <cstdint>

// RRSVM rank-weighted pooling, 3x3 window, stride 2, pad 1.
// x: [32, 64, 112, 112] f32   s: [64, 3, 3] f32
// d_out (f32, concatenated): out [32,64,56,56], order [32,64,56,56,9]

#define BB 32
#define CC 64
#define HH 112
#define WW 112
#define HO 56
#define WO 56
#define PIX_PER_CH (HO * WO)      // 3136
#define NQ (BB * CC)              // 2048
#define TPB 256

__global__ void __launch_bounds__(TPB, 8) rrsvm_kernel(
        const float* __restrict__ x,
        const float* __restrict__ s,
        float* __restrict__ out,
        float* __restrict__ order,
        int write_order) {
    __shared__ __align__(16) float ord_sh[TPB * 9];  // order staging (16B for float4)
    __shared__ float s_sh[18];          // s rows for the (<=2) channels this block touches

    const int tid = threadIdx.x;
    const unsigned p0 = blockIdx.x * TPB;
    const unsigned p = p0 + tid;

    const int q_first = (int)(p0 / PIX_PER_CH);
    const int q = (int)(p / PIX_PER_CH);

    // Load the 1-2 needed s rows (9 floats each) into shared.
    if (tid < 18) {
        int qq = q_first + tid / 9;
        if (qq < NQ) s_sh[tid] = s[(qq & (CC - 1)) * 9 + (tid % 9)];
    }
    __syncthreads();

    const int cbase = (q - q_first) * 9;   // 0 or 9
    const int pix = (int)(p % PIX_PER_CH);
    const int wo = pix % WO;
    const int ho = pix / WO;
    const int lane = tid & 31;

    const float* xp = x + (unsigned)q * (HH * WW);

    // Window rows: h = 2ho-1+i; only i=0 can be out of range (ho==0).
    // Cols 2wo, 2wo+1: always valid, 8B-aligned -> dense float2 load.
    // Col 2wo-1: equals lane-1's bc.y (wo contiguous within warp; warps
    // never straddle a channel since 3136 % 32 == 0). Lane 0 does a scalar
    // fixup load; wo==0 is padding (0); ho==0 row-0 is padding (0).
    float v[9];
    #pragma unroll
    for (int i = 0; i < 3; i++) {
        const int h = 2 * ho - 1 + i;
        const bool hv = (i == 0) ? (ho > 0) : true;
        const float* row = xp + h * WW;
        float2 bc = make_float2(0.0f, 0.0f);
        if (hv) bc = *(const float2*)(row + 2 * wo);
        float left = __shfl_up_sync(0xffffffffu, bc.y, 1);
        if (lane == 0 && wo > 0 && hv) left = __ldg(row + 2 * wo - 1);
        if (wo == 0 || !hv) left = 0.0f;
        v[i * 3]     = left;
        v[i * 3 + 1] = bc.x;
        v[i * 3 + 2] = bc.y;
    }

    // Pairwise ranks scaled by 4 (byte offsets), accumulated with FFMA-imm
    // (rt=1 on fma pipe). m = (v[j] > v[i]) ? 1.0f : 0.0f; strict-greater
    // => ties keep index order (stable argsort of -v). Exact small ints.
    float rf[9];
    #pragma unroll
    for (int k = 0; k < 9; k++) rf[k] = (float)(4 * k);
    #pragma unroll
    for (int i = 0; i < 8; i++) {
        #pragma unroll
        for (int j = i + 1; j < 9; j++) {
            float m;
            asm("set.gt.f32.f32 %0, %1, %2;"
                : "=f"(m) : "f"(v[j]), "f"(v[i]));
            rf[i] = fmaf(m,  4.0f, rf[i]);   // v[j] wins: i ranks one later
            rf[j] = fmaf(m, -4.0f, rf[j]);   // j ranks one earlier
        }
    }
    int ir[9];   // 4 * rank_k (byte offset)
    #pragma unroll
    for (int k = 0; k < 9; k++) ir[k] = (int)rf[k];

    // Weighted sum: out = sum_k v[k] * s[rank_k]
    const char* sp = (const char*)(s_sh + cbase);
    float sum = 0.0f;
    #pragma unroll
    for (int k = 0; k < 9; k++) {
        sum += v[k] * *(const float*)(sp + ir[k]);
    }
    out[p] = sum;

    if (write_order) {
        // Scatter order indices: segment[rank_k] = k  (as float).
        char* my = (char*)(ord_sh + tid * 9);
        #pragma unroll
        for (int k = 0; k < 9; k++) {
            *(float*)(my + ir[k]) = (float)k;
        }
        __syncwarp();
        // Warp-coalesced vectorized copy-out: 288 floats = 72 float4 per warp.
        const int w = tid >> 5;
        const float4* src = (const float4*)(ord_sh + w * 288);
        float4* dst = (float4*)(order + (p0 + (unsigned)w * 32) * 9);
        dst[lane]      = src[lane];
        dst[lane + 32] = src[lane + 32];
        if (lane < 8) dst[lane + 64] = src[lane + 64];
    }
}

extern "C" void kernel_launch(void* const* d_in, const int* in_sizes, int n_in,
                              void* d_out, int out_size) {
    const float* x = (const float*)d_in[0];
    const float* s = (const float*)d_in[1];
    const long long NPIX = (long long)BB * CC * HO * WO;  // 6,422,528

    float* out = (float*)d_out;
    float* order = out + NPIX;
    int write_order = ((long long)out_size >= NPIX * 10LL) ? 1 : 0;

    const long long blocks = (NPIX + TPB - 1) / TPB;  // 25088, exact
    rrsvm_kernel<<<(unsigned)blocks, TPB>>>(x, s, out, order, write_order);
}